// round 4
// baseline (speedup 1.0000x reference)
#include <cuda_runtime.h>
#include <cuda_bf16.h>
#include <cstdint>

// XLSTM social pooling (N=256 agents, B=64, H=128, last timestep only):
// out[i,b,:] = mean over j!=i with ||p_i-p_j||<=r of h_last[j,b,:]
//
// R2 changes vs R1 (18.9us, latency-bound: occ 23%, issue 37%):
//  - 1024 threads/block (32 warps/SM instead of 16) -> hide LDS latency
//  - packed add.rn.f32x2 accumulate (2 instr/neighbor instead of 4 FFMA)
//  - 1-deep software pipeline in the neighbor bit loop (prefetch next row)

#define NA   256
#define NB   64
#define SEQL 20
#define HID  128

#define I_PER_BLOCK 128          // 2 blocks per batch
#define THREADS     1024         // 32 warps -> 4 agents per warp
#define NWARPS      (THREADS / 32)
#define SMEM_BYTES  (NA * HID * 4 + NA * 8)

__device__ __forceinline__ void addx2(unsigned long long& acc, unsigned long long v) {
    asm("add.rn.f32x2 %0, %1, %2;" : "=l"(acc) : "l"(acc), "l"(v));
}

__global__ __launch_bounds__(THREADS, 1)
void social_pool_kernel(const float* __restrict__ hidden,
                        const float* __restrict__ pos,
                        const float* __restrict__ radius_ptr,
                        float* __restrict__ out)
{
    extern __shared__ float smem[];
    float*  hs = smem;                          // [256][128] f32
    float2* ps = (float2*)(smem + NA * HID);    // [256]

    const int b     = blockIdx.x >> 1;
    const int ihalf = blockIdx.x & 1;

    // --- stage positions (last timestep) ---
    for (int j = threadIdx.x; j < NA; j += THREADS) {
        const float* pp = pos + ((size_t)(j * NB + b) * SEQL + (SEQL - 1)) * 2;
        ps[j] = make_float2(pp[0], pp[1]);
    }

    // --- stage h_last tile [256][128] (float4 loads, coalesced 512B rows) ---
    #pragma unroll
    for (int t = threadIdx.x; t < NA * (HID / 4); t += THREADS) {
        const int j = t >> 5;
        const int c = t & 31;
        const float4* src =
            (const float4*)(hidden + ((size_t)(j * NB + b) * SEQL + (SEQL - 1)) * HID) + c;
        ((float4*)hs)[t] = *src;
    }
    __syncthreads();

    const float r  = *radius_ptr;
    const float r2 = r * r;

    const int warp = threadIdx.x >> 5;
    const int lane = threadIdx.x & 31;

    #pragma unroll
    for (int ii = warp; ii < I_PER_BLOCK; ii += NWARPS) {
        const int i = ihalf * I_PER_BLOCK + ii;
        const float2 pi = ps[i];

        unsigned long long a01 = 0ull, a23 = 0ull;   // packed f32x2 accumulators
        int cnt = 0;

        #pragma unroll
        for (int jb = 0; jb < NA; jb += 32) {
            const int j = jb + lane;
            const float2 pj = ps[j];
            const float dx = pi.x - pj.x;
            const float dy = pi.y - pj.y;
            const bool ok = (dx * dx + dy * dy <= r2) && (j != i);
            unsigned m = __ballot_sync(0xffffffffu, ok);
            cnt += __popc(m);

            if (m) {
                int bit = __ffs(m) - 1;
                m &= m - 1;
                ulonglong2 hv =
                    ((const ulonglong2*)(hs + (jb + bit) * HID))[lane];
                while (m) {
                    const int nb = __ffs(m) - 1;
                    m &= m - 1;
                    ulonglong2 nx =
                        ((const ulonglong2*)(hs + (jb + nb) * HID))[lane];
                    addx2(a01, hv.x);
                    addx2(a23, hv.y);
                    hv = nx;
                }
                addx2(a01, hv.x);
                addx2(a23, hv.y);
            }
        }

        const float scale = 1.0f / fmaxf((float)cnt, 1.0f);
        float2 v01 = *(float2*)&a01;
        float2 v23 = *(float2*)&a23;
        float4 o;
        o.x = v01.x * scale; o.y = v01.y * scale;
        o.z = v23.x * scale; o.w = v23.y * scale;
        ((float4*)(out + ((size_t)i * NB + b) * HID))[lane] = o;
    }
}

extern "C" void kernel_launch(void* const* d_in, const int* in_sizes, int n_in,
                              void* d_out, int out_size)
{
    const float* hidden = (const float*)d_in[0];   // (256,64,20,128) f32
    const float* pos    = (const float*)d_in[1];   // (256,64,20,2)  f32
    const float* radius = (const float*)d_in[2];   // scalar f32
    float* out = (float*)d_out;                    // (256,64,128)   f32

    cudaFuncSetAttribute(social_pool_kernel,
                         cudaFuncAttributeMaxDynamicSharedMemorySize,
                         SMEM_BYTES);

    social_pool_kernel<<<NB * 2, THREADS, SMEM_BYTES>>>(hidden, pos, radius, out);
}

// round 5
// speedup vs baseline: 1.0172x; 1.0172x over previous
#include <cuda_runtime.h>
#include <cuda_bf16.h>
#include <cstdint>

// XLSTM social pooling (N=256 agents, B=64, H=128, last timestep only):
// out[i,b,:] = mean over j!=i with ||p_i-p_j||<=r of h_last[j,b,:]
//
// R2 changes vs R1 (18.9us, latency-bound: occ 23%, issue 37%):
//  - 1024 threads/block (32 warps/SM instead of 16) -> hide LDS latency
//  - packed add.rn.f32x2 accumulate (2 instr/neighbor instead of 4 FFMA)
//  - 1-deep software pipeline in the neighbor bit loop (prefetch next row)

#define NA   256
#define NB   64
#define SEQL 20
#define HID  128

#define I_PER_BLOCK 128          // 2 blocks per batch
#define THREADS     1024         // 32 warps -> 4 agents per warp
#define NWARPS      (THREADS / 32)
#define SMEM_BYTES  (NA * HID * 4 + NA * 8)

__device__ __forceinline__ void addx2(unsigned long long& acc, unsigned long long v) {
    asm("add.rn.f32x2 %0, %1, %2;" : "=l"(acc) : "l"(acc), "l"(v));
}

__global__ __launch_bounds__(THREADS, 1)
void social_pool_kernel(const float* __restrict__ hidden,
                        const float* __restrict__ pos,
                        const float* __restrict__ radius_ptr,
                        float* __restrict__ out)
{
    extern __shared__ float smem[];
    float*  hs = smem;                          // [256][128] f32
    float2* ps = (float2*)(smem + NA * HID);    // [256]

    const int b     = blockIdx.x >> 1;
    const int ihalf = blockIdx.x & 1;

    // --- stage positions (last timestep) ---
    for (int j = threadIdx.x; j < NA; j += THREADS) {
        const float* pp = pos + ((size_t)(j * NB + b) * SEQL + (SEQL - 1)) * 2;
        ps[j] = make_float2(pp[0], pp[1]);
    }

    // --- stage h_last tile [256][128] (float4 loads, coalesced 512B rows) ---
    #pragma unroll
    for (int t = threadIdx.x; t < NA * (HID / 4); t += THREADS) {
        const int j = t >> 5;
        const int c = t & 31;
        const float4* src =
            (const float4*)(hidden + ((size_t)(j * NB + b) * SEQL + (SEQL - 1)) * HID) + c;
        ((float4*)hs)[t] = *src;
    }
    __syncthreads();

    const float r  = *radius_ptr;
    const float r2 = r * r;

    const int warp = threadIdx.x >> 5;
    const int lane = threadIdx.x & 31;

    #pragma unroll
    for (int ii = warp; ii < I_PER_BLOCK; ii += NWARPS) {
        const int i = ihalf * I_PER_BLOCK + ii;
        const float2 pi = ps[i];

        unsigned long long a01 = 0ull, a23 = 0ull;   // packed f32x2 accumulators
        int cnt = 0;

        #pragma unroll
        for (int jb = 0; jb < NA; jb += 32) {
            const int j = jb + lane;
            const float2 pj = ps[j];
            const float dx = pi.x - pj.x;
            const float dy = pi.y - pj.y;
            const bool ok = (dx * dx + dy * dy <= r2) && (j != i);
            unsigned m = __ballot_sync(0xffffffffu, ok);
            cnt += __popc(m);

            if (m) {
                int bit = __ffs(m) - 1;
                m &= m - 1;
                ulonglong2 hv =
                    ((const ulonglong2*)(hs + (jb + bit) * HID))[lane];
                while (m) {
                    const int nb = __ffs(m) - 1;
                    m &= m - 1;
                    ulonglong2 nx =
                        ((const ulonglong2*)(hs + (jb + nb) * HID))[lane];
                    addx2(a01, hv.x);
                    addx2(a23, hv.y);
                    hv = nx;
                }
                addx2(a01, hv.x);
                addx2(a23, hv.y);
            }
        }

        const float scale = 1.0f / fmaxf((float)cnt, 1.0f);
        float2 v01 = *(float2*)&a01;
        float2 v23 = *(float2*)&a23;
        float4 o;
        o.x = v01.x * scale; o.y = v01.y * scale;
        o.z = v23.x * scale; o.w = v23.y * scale;
        ((float4*)(out + ((size_t)i * NB + b) * HID))[lane] = o;
    }
}

extern "C" void kernel_launch(void* const* d_in, const int* in_sizes, int n_in,
                              void* d_out, int out_size)
{
    const float* hidden = (const float*)d_in[0];   // (256,64,20,128) f32
    const float* pos    = (const float*)d_in[1];   // (256,64,20,2)  f32
    const float* radius = (const float*)d_in[2];   // scalar f32
    float* out = (float*)d_out;                    // (256,64,128)   f32

    cudaFuncSetAttribute(social_pool_kernel,
                         cudaFuncAttributeMaxDynamicSharedMemorySize,
                         SMEM_BYTES);

    social_pool_kernel<<<NB * 2, THREADS, SMEM_BYTES>>>(hidden, pos, radius, out);
}

// round 6
// speedup vs baseline: 1.0194x; 1.0022x over previous
#include <cuda_runtime.h>
#include <cuda_bf16.h>
#include <cstdint>

// XLSTM social pooling (N=256 agents, B=64, H=128, last timestep only):
// out[i,b,:] = mean over j!=i with ||p_i-p_j||<=r of h_last[j,b,:]
//
// R6: two-phase per agent.
//  Phase 1: ballot + prefix-popc scatter builds a uint16 neighbor-index list
//           (per-warp smem scratch), padded to a multiple of 4 with a dummy
//           index (256) that points at an all-zero smem row.
//  Phase 2: uniform drain loop, 4 visits per iteration: 1 LDS.64 of packed
//           indices + 4 independent LDS.128 row loads (MLP=4) + 8 f32x2 adds.
// Removes the data-dependent while(ffs) loop (MLP=1 + taken branch per visit)
// that kept R5 at issue=53% / L1=35%.

#define NA    256
#define NROWS 257                 // +1 all-zero padding row
#define NB    64
#define SEQL  20
#define HID   128

#define I_PER_BLOCK 128           // 2 blocks per batch
#define THREADS     1024          // 32 warps -> 4 agents per warp
#define NWARPS      (THREADS / 32)
#define SMEM_BYTES  (NROWS * HID * 4 + NA * 8 + NWARPS * NA * 2)

__device__ __forceinline__ void addx2(unsigned long long& acc, unsigned long long v) {
    asm("add.rn.f32x2 %0, %1, %2;" : "=l"(acc) : "l"(acc), "l"(v));
}

__global__ __launch_bounds__(THREADS, 1)
void social_pool_kernel(const float* __restrict__ hidden,
                        const float* __restrict__ pos,
                        const float* __restrict__ radius_ptr,
                        float* __restrict__ out)
{
    extern __shared__ float smem[];
    float*    hs    = smem;                              // [257][128] f32
    float2*   ps    = (float2*)(smem + NROWS * HID);     // [256]
    uint16_t* lists = (uint16_t*)(ps + NA);              // [32][256]

    const int b     = blockIdx.x >> 1;
    const int ihalf = blockIdx.x & 1;

    // --- stage positions (last timestep) ---
    for (int j = threadIdx.x; j < NA; j += THREADS) {
        const float* pp = pos + ((size_t)(j * NB + b) * SEQL + (SEQL - 1)) * 2;
        ps[j] = make_float2(pp[0], pp[1]);
    }

    // --- stage h_last tile [256][128] (float4, coalesced 512B rows) ---
    #pragma unroll
    for (int t = threadIdx.x; t < NA * (HID / 4); t += THREADS) {
        const int j = t >> 5;
        const int c = t & 31;
        const float4* src =
            (const float4*)(hidden + ((size_t)(j * NB + b) * SEQL + (SEQL - 1)) * HID) + c;
        ((float4*)hs)[t] = *src;
    }
    // zero padding row 256 (32 float4)
    if (threadIdx.x < HID / 4) {
        ((float4*)(hs + NA * HID))[threadIdx.x] = make_float4(0.f, 0.f, 0.f, 0.f);
    }
    __syncthreads();

    const float r  = *radius_ptr;
    const float r2 = r * r;

    const int warp = threadIdx.x >> 5;
    const int lane = threadIdx.x & 31;
    const unsigned lmask_lt = (1u << lane) - 1u;

    uint16_t*       mylist = lists + warp * NA;
    const uint64_t* lw     = (const uint64_t*)mylist;

    for (int ii = warp; ii < I_PER_BLOCK; ii += NWARPS) {
        const int i = ihalf * I_PER_BLOCK + ii;
        const float2 pi = ps[i];

        // --- phase 1: build neighbor index list ---
        int cnt = 0;
        #pragma unroll
        for (int w = 0; w < 8; w++) {
            const int j = w * 32 + lane;
            const float2 pj = ps[j];
            const float dx = pi.x - pj.x;
            const float dy = pi.y - pj.y;
            const bool ok = (dx * dx + dy * dy <= r2) && (j != i);
            const unsigned m = __ballot_sync(0xffffffffu, ok);
            if (ok) mylist[cnt + __popc(m & lmask_lt)] = (uint16_t)j;
            cnt += __popc(m);
        }
        // pad to multiple of 4 with dummy index -> zero row
        const int pad = (-cnt) & 3;
        if (lane < pad) mylist[cnt + lane] = (uint16_t)NA;
        __syncwarp();

        // --- phase 2: uniform drain, 4 visits per iteration ---
        unsigned long long a01 = 0ull, a23 = 0ull;
        const int n4 = (cnt + 3) >> 2;
        for (int n = 0; n < n4; n++) {
            const uint64_t q = lw[n];                 // LDS.64 broadcast
            const int j0 = (int)(q        & 0xffff);
            const int j1 = (int)((q >> 16) & 0xffff);
            const int j2 = (int)((q >> 32) & 0xffff);
            const int j3 = (int)(q >> 48);
            const ulonglong2 h0 = ((const ulonglong2*)(hs + j0 * HID))[lane];
            const ulonglong2 h1 = ((const ulonglong2*)(hs + j1 * HID))[lane];
            const ulonglong2 h2 = ((const ulonglong2*)(hs + j2 * HID))[lane];
            const ulonglong2 h3 = ((const ulonglong2*)(hs + j3 * HID))[lane];
            addx2(a01, h0.x); addx2(a23, h0.y);
            addx2(a01, h1.x); addx2(a23, h1.y);
            addx2(a01, h2.x); addx2(a23, h2.y);
            addx2(a01, h3.x); addx2(a23, h3.y);
        }

        const float scale = 1.0f / fmaxf((float)cnt, 1.0f);
        const float2 v01 = *(const float2*)&a01;
        const float2 v23 = *(const float2*)&a23;
        float4 o;
        o.x = v01.x * scale; o.y = v01.y * scale;
        o.z = v23.x * scale; o.w = v23.y * scale;
        ((float4*)(out + ((size_t)i * NB + b) * HID))[lane] = o;

        __syncwarp();   // list reuse fence before next agent's build
    }
}

extern "C" void kernel_launch(void* const* d_in, const int* in_sizes, int n_in,
                              void* d_out, int out_size)
{
    const float* hidden = (const float*)d_in[0];   // (256,64,20,128) f32
    const float* pos    = (const float*)d_in[1];   // (256,64,20,2)  f32
    const float* radius = (const float*)d_in[2];   // scalar f32
    float* out = (float*)d_out;                    // (256,64,128)   f32

    cudaFuncSetAttribute(social_pool_kernel,
                         cudaFuncAttributeMaxDynamicSharedMemorySize,
                         SMEM_BYTES);

    social_pool_kernel<<<NB * 2, THREADS, SMEM_BYTES>>>(hidden, pos, radius, out);
}